// round 7
// baseline (speedup 1.0000x reference)
#include <cuda_runtime.h>
#include <cuda_bf16.h>

// Problem constants
//   I     [64, 64, 8192] f32
//   gamma [64], beta [64]
//   W     [128, 64, 7]
//   alpha [128, 1]
//   out   [64, 128, 4096] f32
#define N_  64
#define C_  64
#define L_  8192
#define O_  128
#define K_  7
#define LOUT_ 4096

// Scratch (device globals; no allocations allowed)
__device__ float    g_ps[N_ * C_];          // per-(n,c) partial sum
__device__ float    g_pq[N_ * C_];          // per-(n,c) partial sumsq
__device__ float    g_thresh[C_];           // per-channel binarization threshold
__device__ unsigned g_bits[N_ * C_ * (L_/32)]; // 4 MB packed signs

// ---------------------------------------------------------------------------
// Kernel 1: per-(n,c) row reduction -> partial sum / sumsq
// grid = 4096 (r = n*64 + c), block = 256
// ---------------------------------------------------------------------------
__global__ void k_stats1(const float* __restrict__ I) {
    const int r = blockIdx.x;
    const float4* p = reinterpret_cast<const float4*>(I + (size_t)r * L_);
    float s = 0.f, q = 0.f;
    for (int i = threadIdx.x; i < L_ / 4; i += 256) {
        float4 v = p[i];
        s += v.x + v.y + v.z + v.w;
        q += v.x * v.x + v.y * v.y + v.z * v.z + v.w * v.w;
    }
    // warp reduce
    #pragma unroll
    for (int o = 16; o; o >>= 1) {
        s += __shfl_down_sync(0xFFFFFFFFu, s, o);
        q += __shfl_down_sync(0xFFFFFFFFu, q, o);
    }
    __shared__ float ss[8], sq[8];
    const int w = threadIdx.x >> 5, lane = threadIdx.x & 31;
    if (lane == 0) { ss[w] = s; sq[w] = q; }
    __syncthreads();
    if (w == 0) {
        s = (lane < 8) ? ss[lane] : 0.f;
        q = (lane < 8) ? sq[lane] : 0.f;
        #pragma unroll
        for (int o = 4; o; o >>= 1) {
            s += __shfl_down_sync(0xFFFFFFFFu, s, o);
            q += __shfl_down_sync(0xFFFFFFFFu, q, o);
        }
        if (lane == 0) { g_ps[r] = s; g_pq[r] = q; }
    }
}

// ---------------------------------------------------------------------------
// Kernel 2: finalize stats per channel, compute threshold
//   x = (I - mean)*rsqrt(var+eps)*gamma + beta >= 0
//     <=> I >= mean - beta*sqrt(var+eps)/gamma     (gamma > 0 guaranteed)
// grid = 64 (c), block = 64 (n)
// ---------------------------------------------------------------------------
__global__ void k_stats2(const float* __restrict__ gamma,
                         const float* __restrict__ beta) {
    const int c = blockIdx.x;
    const int n = threadIdx.x;
    float s = g_ps[n * C_ + c];
    float q = g_pq[n * C_ + c];
    #pragma unroll
    for (int o = 16; o; o >>= 1) {
        s += __shfl_down_sync(0xFFFFFFFFu, s, o);
        q += __shfl_down_sync(0xFFFFFFFFu, q, o);
    }
    __shared__ float s1, q1;
    if (threadIdx.x == 32) { s1 = s; q1 = q; }
    __syncthreads();
    if (threadIdx.x == 0) {
        s += s1; q += q1;
        const float invn = 1.f / ((float)N_ * (float)L_);
        float mean = s * invn;
        float var  = fmaf(-mean, mean, q * invn);
        float inv  = rsqrtf(var + 1e-5f);
        g_thresh[c] = mean - beta[c] / (inv * gamma[c]);
    }
}

// ---------------------------------------------------------------------------
// Kernel 3: binarize to packed bits. bit l of word = (I >= thresh)
// grid = 4096 (r = n*64 + c), block = 256 (one 32-bit word per thread)
// ---------------------------------------------------------------------------
__global__ void k_binarize(const float* __restrict__ I) {
    const int r = blockIdx.x;
    const float t = g_thresh[r & (C_ - 1)];
    const float4* p = reinterpret_cast<const float4*>(
        I + (size_t)r * L_ + threadIdx.x * 32);
    unsigned b = 0;
    #pragma unroll
    for (int i = 0; i < 8; i++) {
        float4 v = p[i];
        b |= (v.x >= t ? 1u : 0u) << (i * 4 + 0);
        b |= (v.y >= t ? 1u : 0u) << (i * 4 + 1);
        b |= (v.z >= t ? 1u : 0u) << (i * 4 + 2);
        b |= (v.w >= t ? 1u : 0u) << (i * 4 + 3);
    }
    g_bits[r * (L_ / 32) + threadIdx.x] = b;
}

// ---------------------------------------------------------------------------
// Kernel 4: conv(K=7, pad 3) + alpha scale + maxpool(2)
// grid = (L/128, Cout/32, N); block = 128 threads
// thread = 8 conv positions x 4 out-channels (32 accumulators)
// smem: signs 64x136 f32 (zero for padded positions -> matches zero-pad conv)
//       weights [c][k][32 out-channels] f32
// ---------------------------------------------------------------------------
#define TL 128           // conv positions per block
#define OG 32            // out channels per block
#define SROW 136         // padded sign row (134 used, float4-load safety)

__global__ void __launch_bounds__(128)
k_conv(const float* __restrict__ W,
       const float* __restrict__ alpha,
       float* __restrict__ out) {
    extern __shared__ float sm[];
    float* sm_s = sm;                    // 64 * 136
    float* sm_w = sm + C_ * SROW;        // 64 * 7 * 32, layout [(c*7+k)*32 + ol]

    const int l0  = blockIdx.x * TL;
    const int ogb = blockIdx.y;          // 0..3
    const int n   = blockIdx.z;
    const int tid = threadIdx.x;

    // Load weight tile: contiguous read of W[ogb*32 .. +32) rows, scatter to smem
    {
        const float* Wg = W + (size_t)(ogb * OG) * (C_ * K_);
        for (int i = tid; i < OG * C_ * K_; i += 128) {
            int ol  = i / (C_ * K_);
            int rem = i - ol * (C_ * K_);
            int c   = rem / K_;
            int k   = rem - c * K_;
            sm_w[(c * K_ + k) * OG + ol] = Wg[i];
        }
    }
    // Decode sign tile: sm_s[c][j] = sign at global l = l0 - 3 + j, 0 at pad
    {
        const unsigned* bb = g_bits + (size_t)n * (C_ * (L_ / 32));
        for (int i = tid; i < C_ * SROW; i += 128) {
            int c = i / SROW;
            int j = i - c * SROW;
            int l = l0 - 3 + j;
            float v = 0.f;
            if (l >= 0 && l < L_ && j < 134) {
                unsigned wd = bb[c * (L_ / 32) + (l >> 5)];
                v = ((wd >> (l & 31)) & 1u) ? 1.f : -1.f;
            }
            sm_s[i] = v;
        }
    }
    __syncthreads();

    const int og = tid >> 4;    // 0..7  -> 4 out-channels each
    const int lg = tid & 15;    // 0..15 -> 8 conv positions each
    const int lb = lg * 8;

    float acc[8][4];
    #pragma unroll
    for (int l = 0; l < 8; l++) {
        acc[l][0] = 0.f; acc[l][1] = 0.f; acc[l][2] = 0.f; acc[l][3] = 0.f;
    }

    const float* srow = sm_s + lb;
    const float* wrow = sm_w + og * 4;

    for (int c = 0; c < C_; c++) {
        const float* sc = srow + c * SROW;
        float4 A = *reinterpret_cast<const float4*>(sc);
        float4 B = *reinterpret_cast<const float4*>(sc + 4);
        float4 Cc = *reinterpret_cast<const float4*>(sc + 8);
        float4 D = *reinterpret_cast<const float4*>(sc + 12);
        float sv[16] = {A.x, A.y, A.z, A.w,  B.x, B.y, B.z, B.w,
                        Cc.x, Cc.y, Cc.z, Cc.w,  D.x, D.y, D.z, D.w};
        const float* wc = wrow + c * (K_ * OG);
        #pragma unroll
        for (int k = 0; k < K_; k++) {
            float4 w = *reinterpret_cast<const float4*>(wc + k * OG);
            #pragma unroll
            for (int l = 0; l < 8; l++) {
                float s = sv[l + k];
                acc[l][0] = fmaf(s, w.x, acc[l][0]);
                acc[l][1] = fmaf(s, w.y, acc[l][1]);
                acc[l][2] = fmaf(s, w.z, acc[l][2]);
                acc[l][3] = fmaf(s, w.w, acc[l][3]);
            }
        }
    }

    // Epilogue: alpha (>0) scale + maxpool2, float4 coalesced stores
    const int o0 = ogb * OG + og * 4;
    const float a0 = alpha[o0 + 0];
    const float a1 = alpha[o0 + 1];
    const float a2 = alpha[o0 + 2];
    const float a3 = alpha[o0 + 3];
    const int lp0 = (l0 >> 1) + lg * 4;

    #pragma unroll
    for (int oo = 0; oo < 4; oo++) {
        float av = (oo == 0) ? a0 : (oo == 1) ? a1 : (oo == 2) ? a2 : a3;
        float4 r;
        r.x = fmaxf(acc[0][oo], acc[1][oo]) * av;
        r.y = fmaxf(acc[2][oo], acc[3][oo]) * av;
        r.z = fmaxf(acc[4][oo], acc[5][oo]) * av;
        r.w = fmaxf(acc[6][oo], acc[7][oo]) * av;
        *reinterpret_cast<float4*>(
            out + ((size_t)(n * O_ + o0 + oo)) * LOUT_ + lp0) = r;
    }
}

// ---------------------------------------------------------------------------
extern "C" void kernel_launch(void* const* d_in, const int* in_sizes, int n_in,
                              void* d_out, int out_size) {
    const float* I     = (const float*)d_in[0];
    const float* gamma = (const float*)d_in[1];
    const float* beta  = (const float*)d_in[2];
    const float* W     = (const float*)d_in[3];
    const float* alpha = (const float*)d_in[4];
    float* out = (float*)d_out;

    k_stats1<<<N_ * C_, 256>>>(I);
    k_stats2<<<C_, 64>>>(gamma, beta);
    k_binarize<<<N_ * C_, 256>>>(I);

    const size_t smem = (size_t)(C_ * SROW + C_ * K_ * OG) * sizeof(float); // 92160 B
    cudaFuncSetAttribute(k_conv, cudaFuncAttributeMaxDynamicSharedMemorySize,
                         (int)smem);
    dim3 grid(L_ / TL, O_ / OG, N_);   // (64, 4, 64)
    k_conv<<<grid, 128, smem>>>(W, alpha, out);
}

// round 8
// speedup vs baseline: 1.0012x; 1.0012x over previous
#include <cuda_runtime.h>
#include <cuda_bf16.h>

// Problem constants
//   I     [64, 64, 8192] f32
//   gamma [64], beta [64]
//   W     [128, 64, 7]
//   alpha [128, 1]
//   out   [64, 128, 4096] f32
#define N_  64
#define C_  64
#define L_  8192
#define O_  128
#define K_  7
#define LOUT_ 4096

// Scratch (device globals; no allocations allowed)
__device__ float    g_ps[N_ * C_];          // per-(n,c) partial sum
__device__ float    g_pq[N_ * C_];          // per-(n,c) partial sumsq
__device__ float    g_thresh[C_];           // per-channel binarization threshold
__device__ unsigned g_bits[N_ * C_ * (L_/32)]; // 4 MB packed signs

// ---------------------------------------------------------------------------
// Kernel 1: per-(n,c) row reduction -> partial sum / sumsq
// grid = 4096 (r = n*64 + c), block = 256
// ---------------------------------------------------------------------------
__global__ void k_stats1(const float* __restrict__ I) {
    const int r = blockIdx.x;
    const float4* p = reinterpret_cast<const float4*>(I + (size_t)r * L_);
    float s = 0.f, q = 0.f;
    for (int i = threadIdx.x; i < L_ / 4; i += 256) {
        float4 v = p[i];
        s += v.x + v.y + v.z + v.w;
        q += v.x * v.x + v.y * v.y + v.z * v.z + v.w * v.w;
    }
    // warp reduce
    #pragma unroll
    for (int o = 16; o; o >>= 1) {
        s += __shfl_down_sync(0xFFFFFFFFu, s, o);
        q += __shfl_down_sync(0xFFFFFFFFu, q, o);
    }
    __shared__ float ss[8], sq[8];
    const int w = threadIdx.x >> 5, lane = threadIdx.x & 31;
    if (lane == 0) { ss[w] = s; sq[w] = q; }
    __syncthreads();
    if (w == 0) {
        s = (lane < 8) ? ss[lane] : 0.f;
        q = (lane < 8) ? sq[lane] : 0.f;
        #pragma unroll
        for (int o = 4; o; o >>= 1) {
            s += __shfl_down_sync(0xFFFFFFFFu, s, o);
            q += __shfl_down_sync(0xFFFFFFFFu, q, o);
        }
        if (lane == 0) { g_ps[r] = s; g_pq[r] = q; }
    }
}

// ---------------------------------------------------------------------------
// Kernel 2: finalize stats per channel, compute threshold
//   x = (I - mean)*rsqrt(var+eps)*gamma + beta >= 0
//     <=> I >= mean - beta*sqrt(var+eps)/gamma     (gamma > 0 guaranteed)
// grid = 64 (c), block = 64 (n)
// ---------------------------------------------------------------------------
__global__ void k_stats2(const float* __restrict__ gamma,
                         const float* __restrict__ beta) {
    const int c = blockIdx.x;
    const int n = threadIdx.x;
    float s = g_ps[n * C_ + c];
    float q = g_pq[n * C_ + c];
    #pragma unroll
    for (int o = 16; o; o >>= 1) {
        s += __shfl_down_sync(0xFFFFFFFFu, s, o);
        q += __shfl_down_sync(0xFFFFFFFFu, q, o);
    }
    __shared__ float s1, q1;
    if (threadIdx.x == 32) { s1 = s; q1 = q; }
    __syncthreads();
    if (threadIdx.x == 0) {
        s += s1; q += q1;
        const float invn = 1.f / ((float)N_ * (float)L_);
        float mean = s * invn;
        float var  = fmaf(-mean, mean, q * invn);
        float inv  = rsqrtf(var + 1e-5f);
        g_thresh[c] = mean - beta[c] / (inv * gamma[c]);
    }
}

// ---------------------------------------------------------------------------
// Kernel 3: binarize to packed bits. bit l of word = (I >= thresh)
// grid = 4096 (r = n*64 + c), block = 256 (one 32-bit word per thread)
// ---------------------------------------------------------------------------
__global__ void k_binarize(const float* __restrict__ I) {
    const int r = blockIdx.x;
    const float t = g_thresh[r & (C_ - 1)];
    const float4* p = reinterpret_cast<const float4*>(
        I + (size_t)r * L_ + threadIdx.x * 32);
    unsigned b = 0;
    #pragma unroll
    for (int i = 0; i < 8; i++) {
        float4 v = p[i];
        b |= (v.x >= t ? 1u : 0u) << (i * 4 + 0);
        b |= (v.y >= t ? 1u : 0u) << (i * 4 + 1);
        b |= (v.z >= t ? 1u : 0u) << (i * 4 + 2);
        b |= (v.w >= t ? 1u : 0u) << (i * 4 + 3);
    }
    g_bits[r * (L_ / 32) + threadIdx.x] = b;
}

// ---------------------------------------------------------------------------
// Kernel 4: conv(K=7, pad 3) + alpha scale + maxpool(2)
// grid = (L/128, Cout/32, N); block = 128 threads
// thread = 8 conv positions x 4 out-channels (32 accumulators)
// smem: signs 64x136 f32 (zero for padded positions -> matches zero-pad conv)
//       weights [c][k][32 out-channels] f32
// ---------------------------------------------------------------------------
#define TL 128           // conv positions per block
#define OG 32            // out channels per block
#define SROW 136         // padded sign row (134 used, float4-load safety)

__global__ void __launch_bounds__(128)
k_conv(const float* __restrict__ W,
       const float* __restrict__ alpha,
       float* __restrict__ out) {
    extern __shared__ float sm[];
    float* sm_s = sm;                    // 64 * 136
    float* sm_w = sm + C_ * SROW;        // 64 * 7 * 32, layout [(c*7+k)*32 + ol]

    const int l0  = blockIdx.x * TL;
    const int ogb = blockIdx.y;          // 0..3
    const int n   = blockIdx.z;
    const int tid = threadIdx.x;

    // Load weight tile: contiguous read of W[ogb*32 .. +32) rows, scatter to smem
    {
        const float* Wg = W + (size_t)(ogb * OG) * (C_ * K_);
        for (int i = tid; i < OG * C_ * K_; i += 128) {
            int ol  = i / (C_ * K_);
            int rem = i - ol * (C_ * K_);
            int c   = rem / K_;
            int k   = rem - c * K_;
            sm_w[(c * K_ + k) * OG + ol] = Wg[i];
        }
    }
    // Decode sign tile: sm_s[c][j] = sign at global l = l0 - 3 + j, 0 at pad
    {
        const unsigned* bb = g_bits + (size_t)n * (C_ * (L_ / 32));
        for (int i = tid; i < C_ * SROW; i += 128) {
            int c = i / SROW;
            int j = i - c * SROW;
            int l = l0 - 3 + j;
            float v = 0.f;
            if (l >= 0 && l < L_ && j < 134) {
                unsigned wd = bb[c * (L_ / 32) + (l >> 5)];
                v = ((wd >> (l & 31)) & 1u) ? 1.f : -1.f;
            }
            sm_s[i] = v;
        }
    }
    __syncthreads();

    const int og = tid >> 4;    // 0..7  -> 4 out-channels each
    const int lg = tid & 15;    // 0..15 -> 8 conv positions each
    const int lb = lg * 8;

    float acc[8][4];
    #pragma unroll
    for (int l = 0; l < 8; l++) {
        acc[l][0] = 0.f; acc[l][1] = 0.f; acc[l][2] = 0.f; acc[l][3] = 0.f;
    }

    const float* srow = sm_s + lb;
    const float* wrow = sm_w + og * 4;

    for (int c = 0; c < C_; c++) {
        const float* sc = srow + c * SROW;
        float4 A = *reinterpret_cast<const float4*>(sc);
        float4 B = *reinterpret_cast<const float4*>(sc + 4);
        float4 Cc = *reinterpret_cast<const float4*>(sc + 8);
        float4 D = *reinterpret_cast<const float4*>(sc + 12);
        float sv[16] = {A.x, A.y, A.z, A.w,  B.x, B.y, B.z, B.w,
                        Cc.x, Cc.y, Cc.z, Cc.w,  D.x, D.y, D.z, D.w};
        const float* wc = wrow + c * (K_ * OG);
        #pragma unroll
        for (int k = 0; k < K_; k++) {
            float4 w = *reinterpret_cast<const float4*>(wc + k * OG);
            #pragma unroll
            for (int l = 0; l < 8; l++) {
                float s = sv[l + k];
                acc[l][0] = fmaf(s, w.x, acc[l][0]);
                acc[l][1] = fmaf(s, w.y, acc[l][1]);
                acc[l][2] = fmaf(s, w.z, acc[l][2]);
                acc[l][3] = fmaf(s, w.w, acc[l][3]);
            }
        }
    }

    // Epilogue: alpha (>0) scale + maxpool2, float4 coalesced stores
    const int o0 = ogb * OG + og * 4;
    const float a0 = alpha[o0 + 0];
    const float a1 = alpha[o0 + 1];
    const float a2 = alpha[o0 + 2];
    const float a3 = alpha[o0 + 3];
    const int lp0 = (l0 >> 1) + lg * 4;

    #pragma unroll
    for (int oo = 0; oo < 4; oo++) {
        float av = (oo == 0) ? a0 : (oo == 1) ? a1 : (oo == 2) ? a2 : a3;
        float4 r;
        r.x = fmaxf(acc[0][oo], acc[1][oo]) * av;
        r.y = fmaxf(acc[2][oo], acc[3][oo]) * av;
        r.z = fmaxf(acc[4][oo], acc[5][oo]) * av;
        r.w = fmaxf(acc[6][oo], acc[7][oo]) * av;
        *reinterpret_cast<float4*>(
            out + ((size_t)(n * O_ + o0 + oo)) * LOUT_ + lp0) = r;
    }
}

// ---------------------------------------------------------------------------
extern "C" void kernel_launch(void* const* d_in, const int* in_sizes, int n_in,
                              void* d_out, int out_size) {
    const float* I     = (const float*)d_in[0];
    const float* gamma = (const float*)d_in[1];
    const float* beta  = (const float*)d_in[2];
    const float* W     = (const float*)d_in[3];
    const float* alpha = (const float*)d_in[4];
    float* out = (float*)d_out;

    k_stats1<<<N_ * C_, 256>>>(I);
    k_stats2<<<C_, 64>>>(gamma, beta);
    k_binarize<<<N_ * C_, 256>>>(I);

    const size_t smem = (size_t)(C_ * SROW + C_ * K_ * OG) * sizeof(float); // 92160 B
    cudaFuncSetAttribute(k_conv, cudaFuncAttributeMaxDynamicSharedMemorySize,
                         (int)smem);
    dim3 grid(L_ / TL, O_ / OG, N_);   // (64, 4, 64)
    k_conv<<<grid, 128, smem>>>(W, alpha, out);
}